// round 2
// baseline (speedup 1.0000x reference)
#include <cuda_runtime.h>
#include <cuda_bf16.h>
#include <stdint.h>

// Problem shape
#define BB 8
#define NN 3136
#define DD 1536
#define PP 4096
#define MM (BB*NN)      // 25088

// Tiling
#define BM 128
#define BN 128
#define BK 64
#define NKC (DD/BK)     // 24 k-chunks
#define NNT (PP/BN)     // 32 n-tiles
#define THREADS 256

#define SMEM_BYTES (2*BM*64*2 + 2*BN*64*2 + BN*4 + 2*BM*4)  // 67072

// Scratch (allocation-free rule: device globals)
__device__ __nv_bfloat16 g_A[(size_t)MM*DD];   // embeds bf16 (77 MB)
__device__ __nv_bfloat16 g_Bc[(size_t)PP*DD];  // centroids bf16 (12.6 MB)
__device__ float g_nA[MM];                     // ||x||^2
__device__ float g_nB[PP];                     // ||c||^2

// ---------------------------------------------------------------------------
// Prep: fp32 -> bf16 conversion + fp32 squared norms. One block per row.
// ---------------------------------------------------------------------------
__global__ void prep_kernel(const float* __restrict__ embeds,
                            const float* __restrict__ cents,
                            float* __restrict__ out, int loss_elems) {
    int row = blockIdx.x;
    const float* src;
    __nv_bfloat16* dst;
    float* ndst;
    if (row < MM) {
        src = embeds + (size_t)row * DD;
        dst = g_A + (size_t)row * DD;
        ndst = g_nA + row;
    } else {
        int r = row - MM;
        src = cents + (size_t)r * DD;
        dst = g_Bc + (size_t)r * DD;
        ndst = g_nB + r;
    }
    float s = 0.f;
#pragma unroll
    for (int i = 0; i < DD / THREADS; ++i) {
        int j = i * THREADS + threadIdx.x;
        float v = src[j];
        dst[j] = __float2bfloat16(v);
        s += v * v;
    }
#pragma unroll
    for (int off = 16; off; off >>= 1)
        s += __shfl_xor_sync(0xffffffffu, s, off);
    __shared__ float ws[THREADS / 32];
    int lane = threadIdx.x & 31, warp = threadIdx.x >> 5;
    if (lane == 0) ws[warp] = s;
    __syncthreads();
    if (threadIdx.x == 0) {
        float t = 0.f;
#pragma unroll
        for (int w = 0; w < THREADS / 32; ++w) t += ws[w];
        *ndst = t;
    }
    // loss = 0.0 (eval mode) at the front of the output buffer
    if (row == 0 && threadIdx.x < loss_elems) out[threadIdx.x] = 0.f;
}

// ---------------------------------------------------------------------------
// PTX helpers
// ---------------------------------------------------------------------------
__device__ __forceinline__ uint32_t smem_u32(const void* p) {
    return (uint32_t)__cvta_generic_to_shared(p);
}
__device__ __forceinline__ void cp16(void* s, const void* g) {
    asm volatile("cp.async.cg.shared.global [%0], [%1], 16;\n"
                 :: "r"(smem_u32(s)), "l"(g));
}
__device__ __forceinline__ void cp_commit() {
    asm volatile("cp.async.commit_group;\n");
}
template <int N>
__device__ __forceinline__ void cp_wait() {
    asm volatile("cp.async.wait_group %0;\n" :: "n"(N));
}
__device__ __forceinline__ void ldm_x4(uint32_t* r, const __nv_bfloat16* p) {
    asm volatile("ldmatrix.sync.aligned.m8n8.x4.shared.b16 {%0,%1,%2,%3}, [%4];\n"
                 : "=r"(r[0]), "=r"(r[1]), "=r"(r[2]), "=r"(r[3])
                 : "r"(smem_u32(p)));
}
__device__ __forceinline__ void mma_bf16(float* c, const uint32_t* a, const uint32_t* b) {
    asm volatile("mma.sync.aligned.m16n8k16.row.col.f32.bf16.bf16.f32 "
                 "{%0,%1,%2,%3}, {%4,%5,%6,%7}, {%8,%9}, {%0,%1,%2,%3};\n"
                 : "+f"(c[0]), "+f"(c[1]), "+f"(c[2]), "+f"(c[3])
                 : "r"(a[0]), "r"(a[1]), "r"(a[2]), "r"(a[3]),
                   "r"(b[0]), "r"(b[1]));
}

// XOR-swizzled half offset for (row, 16B-chunk c8) in a [128][64]-half tile.
// Conflict-free for ldmatrix reads and 4-phase-perfect for cp.async stores.
__device__ __forceinline__ int swz(int row, int c8) {
    return row * 64 + ((c8 ^ (row & 7)) << 3);
}

// ---------------------------------------------------------------------------
// Main: bf16 MMA GEMM (M=25088, N=4096, K=1536) with running-min epilogue.
// grid = 196 blocks (BM=128 rows each), 8 warps as 4(M) x 2(N).
// ---------------------------------------------------------------------------
__global__ __launch_bounds__(THREADS, 1)
void gemm_min_kernel(float* __restrict__ out, int offset) {
    extern __shared__ __align__(16) char smem_raw[];
    __nv_bfloat16* As = (__nv_bfloat16*)smem_raw;     // 2 x [128][64] halves
    __nv_bfloat16* Bs = As + 2 * BM * 64;             // 2 x [128][64] halves
    float* ncs = (float*)(Bs + 2 * BN * 64);          // [128] centroid norms
    float* partial = ncs + BN;                        // [2][128] cross-warp min

    const int tid = threadIdx.x;
    const int lane = tid & 31, warp = tid >> 5;
    const int wm = warp >> 1, wn = warp & 1;          // 4 x 2 warp grid
    const int m0 = blockIdx.x * BM;

    // per-lane running min of (||c||^2 - 2 x.c); [m-subtile][row-half]
    float rmin[2][2] = {{3.4e38f, 3.4e38f}, {3.4e38f, 3.4e38f}};

    const int arow  = (lane & 7) + ((lane >> 3) & 1) * 8;  // ldmatrix row 0..15
    const int acbit = (lane >> 4) & 1;                     // +8 halves column

    for (int nt = 0; nt < NNT; ++nt) {
        const int p0 = nt * BN;
        __syncthreads();  // previous epilogue done before ncs overwrite
        if (tid < BN) ncs[tid] = g_nB[p0 + tid];

        float acc[2][8][4];
#pragma unroll
        for (int i = 0; i < 2; ++i)
#pragma unroll
            for (int j = 0; j < 8; ++j)
#pragma unroll
                for (int k = 0; k < 4; ++k) acc[i][j][k] = 0.f;

        // prologue: chunk 0 -> buffer 0
        {
            const __nv_bfloat16* Ag = g_A + (size_t)m0 * DD;
            const __nv_bfloat16* Bg = g_Bc + (size_t)p0 * DD;
#pragma unroll
            for (int t = 0; t < 4; ++t) {
                int idx = tid + t * THREADS;
                int row = idx >> 3, c8 = idx & 7;
                cp16(As + swz(row, c8), Ag + (size_t)row * DD + c8 * 8);
                cp16(Bs + swz(row, c8), Bg + (size_t)row * DD + c8 * 8);
            }
            cp_commit();
        }

#pragma unroll 1
        for (int kc = 0; kc < NKC; ++kc) {
            if (kc + 1 < NKC) {  // prefetch next chunk into the other buffer
                int buf = (kc + 1) & 1;
                const __nv_bfloat16* Ag = g_A + (size_t)m0 * DD + (kc + 1) * BK;
                const __nv_bfloat16* Bg = g_Bc + (size_t)p0 * DD + (kc + 1) * BK;
                __nv_bfloat16* Asb = As + buf * BM * 64;
                __nv_bfloat16* Bsb = Bs + buf * BN * 64;
#pragma unroll
                for (int t = 0; t < 4; ++t) {
                    int idx = tid + t * THREADS;
                    int row = idx >> 3, c8 = idx & 7;
                    cp16(Asb + swz(row, c8), Ag + (size_t)row * DD + c8 * 8);
                    cp16(Bsb + swz(row, c8), Bg + (size_t)row * DD + c8 * 8);
                }
                cp_commit();
                cp_wait<1>();
            } else {
                cp_wait<0>();
            }
            __syncthreads();

            const __nv_bfloat16* Asb = As + (kc & 1) * BM * 64;
            const __nv_bfloat16* Bsb = Bs + (kc & 1) * BN * 64;
#pragma unroll
            for (int ks = 0; ks < BK / 16; ++ks) {
                uint32_t a[2][4];
                int c8 = ks * 2 + acbit;
#pragma unroll
                for (int mt = 0; mt < 2; ++mt) {
                    int row = wm * 32 + mt * 16 + arow;
                    ldm_x4(a[mt], Asb + swz(row, c8));
                }
                uint32_t b[8][2];
#pragma unroll
                for (int tp = 0; tp < 4; ++tp) {
                    uint32_t r[4];
                    int row = wn * 64 + tp * 16 + arow;
                    ldm_x4(r, Bsb + swz(row, c8));
                    b[2 * tp][0] = r[0];  b[2 * tp][1] = r[2];
                    b[2 * tp + 1][0] = r[1]; b[2 * tp + 1][1] = r[3];
                }
#pragma unroll
                for (int mt = 0; mt < 2; ++mt)
#pragma unroll
                    for (int j = 0; j < 8; ++j)
                        mma_bf16(acc[mt][j], a[mt], b[j]);
            }
            __syncthreads();
        }

        // epilogue: fold this N-tile into the running min
#pragma unroll
        for (int j = 0; j < 8; ++j) {
            int col = wn * 64 + j * 8 + (lane & 3) * 2;
            float nc0 = ncs[col], nc1 = ncs[col + 1];
#pragma unroll
            for (int mt = 0; mt < 2; ++mt) {
                float v0 = fminf(nc0 - 2.f * acc[mt][j][0],
                                 nc1 - 2.f * acc[mt][j][1]);
                float v1 = fminf(nc0 - 2.f * acc[mt][j][2],
                                 nc1 - 2.f * acc[mt][j][3]);
                rmin[mt][0] = fminf(rmin[mt][0], v0);
                rmin[mt][1] = fminf(rmin[mt][1], v1);
            }
        }
    }

    // reduce across the 4 lanes sharing each row (cols differ by lane&3)
#pragma unroll
    for (int mt = 0; mt < 2; ++mt)
#pragma unroll
        for (int h = 0; h < 2; ++h) {
            float v = rmin[mt][h];
            v = fminf(v, __shfl_xor_sync(0xffffffffu, v, 1));
            v = fminf(v, __shfl_xor_sync(0xffffffffu, v, 2));
            rmin[mt][h] = v;
        }
    __syncthreads();
    if ((lane & 3) == 0) {
        int q = lane >> 2;
#pragma unroll
        for (int mt = 0; mt < 2; ++mt)
#pragma unroll
            for (int h = 0; h < 2; ++h)
                partial[wn * BM + wm * 32 + mt * 16 + h * 8 + q] = rmin[mt][h];
    }
    __syncthreads();
    // combine the two N-warps, add ||x||^2, sqrt, store
    if (tid < BM) {
        float v = fminf(partial[tid], partial[BM + tid]);
        float d2 = g_nA[m0 + tid] + v;
        out[offset + m0 + tid] = sqrtf(fmaxf(d2, 0.f));
    }
}

// ---------------------------------------------------------------------------
extern "C" void kernel_launch(void* const* d_in, const int* in_sizes, int n_in,
                              void* d_out, int out_size) {
    const float* embeds = (const float*)d_in[0];
    const float* cents  = (const float*)d_in[1];
    // guard against swapped metadata order
    if (n_in >= 2 && in_sizes[0] == PP * DD && in_sizes[1] == MM * DD) {
        embeds = (const float*)d_in[1];
        cents  = (const float*)d_in[0];
    }
    float* out = (float*)d_out;
    int loss_elems = out_size - MM;      // 1 if (loss, score) flattened; 0 if score only
    if (loss_elems < 0) loss_elems = 0;

    cudaFuncSetAttribute(gemm_min_kernel,
                         cudaFuncAttributeMaxDynamicSharedMemorySize, SMEM_BYTES);

    prep_kernel<<<MM + PP, THREADS>>>(embeds, cents, out, loss_elems);
    gemm_min_kernel<<<MM / BM, THREADS, SMEM_BYTES>>>(out, loss_elems);
}

// round 4
// speedup vs baseline: 1.5650x; 1.5650x over previous
#include <cuda_runtime.h>
#include <cuda_bf16.h>
#include <stdint.h>

// ---------------- Problem shape ----------------
#define BB 8
#define NN 3136
#define DD 1536
#define PP 4096
#define MM (BB*NN)          // 25088

// ---------------- Tiling ----------------
#define BM 128
#define BN 128
#define BK 64               // k-chunk (128 bytes per row, SW128-style swizzle)
#define NKC (DD/BK)         // 24
#define NMT (MM/BM)         // 196 m-tiles
#define NNT (PP/BN)         // 32 n-tiles
#define NITEMS (NMT*NNT)    // 6272 work items
#define GRID 296            // 2 CTAs per SM on 148 SMs
#define THREADS 256

#define SMEM_BYTES (2*BM*64*2 + 2*BN*64*2)   // 65536 (double-buffered A+B)

// ---------------- Scratch (device globals: allocation-free rule) ------------
__device__ __nv_bfloat16 g_A[(size_t)MM*DD];   // embeds bf16
__device__ __nv_bfloat16 g_Bc[(size_t)PP*DD];  // centroids bf16
__device__ float g_nA[MM];                     // ||x||^2
__device__ float g_nB[PP];                     // ||c||^2
__device__ unsigned int g_min[MM];             // running min of dist^2 (uint bits)

// ---------------------------------------------------------------------------
// Prep: fp32 -> bf16 + fp32 squared norms + init g_min to +inf.
// ---------------------------------------------------------------------------
__global__ void prep_kernel(const float* __restrict__ embeds,
                            const float* __restrict__ cents,
                            float* __restrict__ out, int loss_elems) {
    int row = blockIdx.x;
    const float* src;
    __nv_bfloat16* dst;
    float* ndst;
    if (row < MM) {
        src = embeds + (size_t)row * DD;
        dst = g_A + (size_t)row * DD;
        ndst = g_nA + row;
        if (threadIdx.x == 0) g_min[row] = 0x7F800000u;  // +inf
    } else {
        int r = row - MM;
        src = cents + (size_t)r * DD;
        dst = g_Bc + (size_t)r * DD;
        ndst = g_nB + r;
    }
    float s = 0.f;
#pragma unroll
    for (int i = 0; i < DD / THREADS; ++i) {
        int j = i * THREADS + threadIdx.x;
        float v = src[j];
        dst[j] = __float2bfloat16(v);
        s += v * v;
    }
#pragma unroll
    for (int off = 16; off; off >>= 1)
        s += __shfl_xor_sync(0xffffffffu, s, off);
    __shared__ float ws[THREADS / 32];
    int lane = threadIdx.x & 31, warp = threadIdx.x >> 5;
    if (lane == 0) ws[warp] = s;
    __syncthreads();
    if (threadIdx.x == 0) {
        float t = 0.f;
#pragma unroll
        for (int w = 0; w < THREADS / 32; ++w) t += ws[w];
        *ndst = t;
    }
    if (row == 0 && threadIdx.x < loss_elems) out[threadIdx.x] = 0.f;
}

// ---------------------------------------------------------------------------
// PTX helpers (generic ISA only — no sm_103a-specific instructions)
// ---------------------------------------------------------------------------
__device__ __forceinline__ uint32_t smem_u32(const void* p) {
    return (uint32_t)__cvta_generic_to_shared(p);
}
__device__ __forceinline__ void cp16(void* s, const void* g) {
    asm volatile("cp.async.cg.shared.global [%0], [%1], 16;\n"
                 :: "r"(smem_u32(s)), "l"(g));
}
__device__ __forceinline__ void cp_commit() {
    asm volatile("cp.async.commit_group;\n");
}
template <int N>
__device__ __forceinline__ void cp_wait() {
    asm volatile("cp.async.wait_group %0;\n" :: "n"(N));
}
__device__ __forceinline__ void ldm_x4(uint32_t* r, const __nv_bfloat16* p) {
    asm volatile("ldmatrix.sync.aligned.m8n8.x4.shared.b16 {%0,%1,%2,%3}, [%4];\n"
                 : "=r"(r[0]), "=r"(r[1]), "=r"(r[2]), "=r"(r[3])
                 : "r"(smem_u32(p)));
}
__device__ __forceinline__ void mma_bf16(float* c, const uint32_t* a, const uint32_t* b) {
    asm volatile("mma.sync.aligned.m16n8k16.row.col.f32.bf16.bf16.f32 "
                 "{%0,%1,%2,%3}, {%4,%5,%6,%7}, {%8,%9}, {%0,%1,%2,%3};\n"
                 : "+f"(c[0]), "+f"(c[1]), "+f"(c[2]), "+f"(c[3])
                 : "r"(a[0]), "r"(a[1]), "r"(a[2]), "r"(a[3]),
                   "r"(b[0]), "r"(b[1]));
}
// XOR-swizzled half offset for (row, 16B-chunk c8) in a [rows][64]-half tile.
__device__ __forceinline__ int swz(int row, int c8) {
    return row * 64 + ((c8 ^ (row & 7)) << 3);
}

// ---------------------------------------------------------------------------
// Persistent HMMA GEMM-min. 296 CTAs, 2 resident per SM, 6272 items.
// Item = (m-tile 128) x (n-tile 128), full K=1536, fold min via atomicMin.
// ---------------------------------------------------------------------------
__global__ __launch_bounds__(THREADS, 2)
void gemm_min_kernel() {
    extern __shared__ __align__(16) char smem_raw[];
    __nv_bfloat16* As = (__nv_bfloat16*)smem_raw;     // 2 x [128][64]
    __nv_bfloat16* Bs = As + 2 * BM * 64;             // 2 x [128][64]

    const int tid = threadIdx.x;
    const int lane = tid & 31, warp = tid >> 5;
    const int wm = warp >> 1, wn = warp & 1;          // 4(M) x 2(N) warps

    const int arow  = (lane & 7) + ((lane >> 3) & 1) * 8;
    const int acbit = (lane >> 4) & 1;

    for (int it = blockIdx.x; it < NITEMS; it += GRID) {
        const int m0 = (it >> 5) * BM;
        const int p0 = (it & 31) * BN;

        float acc[2][8][4];
#pragma unroll
        for (int i = 0; i < 2; ++i)
#pragma unroll
            for (int j = 0; j < 8; ++j)
#pragma unroll
                for (int k = 0; k < 4; ++k) acc[i][j][k] = 0.f;

        // prologue: chunk 0 -> buffer 0
        {
            const __nv_bfloat16* Ag = g_A + (size_t)m0 * DD;
            const __nv_bfloat16* Bg = g_Bc + (size_t)p0 * DD;
#pragma unroll
            for (int t = 0; t < 4; ++t) {
                int idx = tid + t * THREADS;
                int row = idx >> 3, c8 = idx & 7;
                cp16(As + swz(row, c8), Ag + (size_t)row * DD + c8 * 8);
                cp16(Bs + swz(row, c8), Bg + (size_t)row * DD + c8 * 8);
            }
            cp_commit();
        }

#pragma unroll 1
        for (int kc = 0; kc < NKC; ++kc) {
            if (kc + 1 < NKC) {
                int buf = (kc + 1) & 1;
                const __nv_bfloat16* Ag = g_A + (size_t)m0 * DD + (kc + 1) * BK;
                const __nv_bfloat16* Bg = g_Bc + (size_t)p0 * DD + (kc + 1) * BK;
                __nv_bfloat16* Asb = As + buf * BM * 64;
                __nv_bfloat16* Bsb = Bs + buf * BN * 64;
#pragma unroll
                for (int t = 0; t < 4; ++t) {
                    int idx = tid + t * THREADS;
                    int row = idx >> 3, c8 = idx & 7;
                    cp16(Asb + swz(row, c8), Ag + (size_t)row * DD + c8 * 8);
                    cp16(Bsb + swz(row, c8), Bg + (size_t)row * DD + c8 * 8);
                }
                cp_commit();
                cp_wait<1>();
            } else {
                cp_wait<0>();
            }
            __syncthreads();

            const __nv_bfloat16* Asb = As + (kc & 1) * BM * 64;
            const __nv_bfloat16* Bsb = Bs + (kc & 1) * BN * 64;
#pragma unroll
            for (int ks = 0; ks < BK / 16; ++ks) {
                uint32_t a[2][4];
                int c8 = ks * 2 + acbit;
#pragma unroll
                for (int mt = 0; mt < 2; ++mt) {
                    int row = wm * 32 + mt * 16 + arow;
                    ldm_x4(a[mt], Asb + swz(row, c8));
                }
                uint32_t b[8][2];
#pragma unroll
                for (int tp = 0; tp < 4; ++tp) {
                    uint32_t r[4];
                    int row = wn * 64 + tp * 16 + arow;
                    ldm_x4(r, Bsb + swz(row, c8));
                    b[2 * tp][0] = r[0];  b[2 * tp][1] = r[2];
                    b[2 * tp + 1][0] = r[1]; b[2 * tp + 1][1] = r[3];
                }
#pragma unroll
                for (int mt = 0; mt < 2; ++mt)
#pragma unroll
                    for (int j = 0; j < 8; ++j)
                        mma_bf16(acc[mt][j], a[mt], b[j]);
            }
            __syncthreads();
        }

        // epilogue: min over this warp's 64 columns, then atomicMin to global
        float rmin[2][2] = {{3.4e38f, 3.4e38f}, {3.4e38f, 3.4e38f}};
#pragma unroll
        for (int j = 0; j < 8; ++j) {
            int col = p0 + wn * 64 + j * 8 + (lane & 3) * 2;
            float nc0 = g_nB[col], nc1 = g_nB[col + 1];
#pragma unroll
            for (int mt = 0; mt < 2; ++mt) {
                float v0 = fminf(nc0 - 2.f * acc[mt][j][0],
                                 nc1 - 2.f * acc[mt][j][1]);
                float v1 = fminf(nc0 - 2.f * acc[mt][j][2],
                                 nc1 - 2.f * acc[mt][j][3]);
                rmin[mt][0] = fminf(rmin[mt][0], v0);
                rmin[mt][1] = fminf(rmin[mt][1], v1);
            }
        }
#pragma unroll
        for (int mt = 0; mt < 2; ++mt)
#pragma unroll
            for (int h = 0; h < 2; ++h) {
                float v = rmin[mt][h];
                v = fminf(v, __shfl_xor_sync(0xffffffffu, v, 1));
                v = fminf(v, __shfl_xor_sync(0xffffffffu, v, 2));
                rmin[mt][h] = v;
            }
        if ((lane & 3) == 0) {
            int q = lane >> 2;
#pragma unroll
            for (int mt = 0; mt < 2; ++mt)
#pragma unroll
                for (int h = 0; h < 2; ++h) {
                    int m = m0 + wm * 32 + mt * 16 + h * 8 + q;
                    float d2 = fmaxf(g_nA[m] + rmin[mt][h], 0.f);
                    atomicMin(&g_min[m], __float_as_uint(d2));
                }
        }
        // no extra barrier needed: last two kc iterations both ended with
        // __syncthreads(), so both smem buffers are free for the next item
    }
}

// ---------------------------------------------------------------------------
// Final: sqrt of the folded min distance^2.
// ---------------------------------------------------------------------------
__global__ void sqrt_kernel(float* __restrict__ out, int offset) {
    int m = blockIdx.x * blockDim.x + threadIdx.x;
    if (m < MM) out[offset + m] = sqrtf(__uint_as_float(g_min[m]));
}

// ---------------------------------------------------------------------------
extern "C" void kernel_launch(void* const* d_in, const int* in_sizes, int n_in,
                              void* d_out, int out_size) {
    const float* embeds = (const float*)d_in[0];
    const float* cents  = (const float*)d_in[1];
    if (n_in >= 2 && in_sizes[0] == PP * DD && in_sizes[1] == MM * DD) {
        embeds = (const float*)d_in[1];
        cents  = (const float*)d_in[0];
    }
    float* out = (float*)d_out;
    int loss_elems = out_size - MM;
    if (loss_elems < 0) loss_elems = 0;

    cudaFuncSetAttribute(gemm_min_kernel,
                         cudaFuncAttributeMaxDynamicSharedMemorySize, SMEM_BYTES);

    prep_kernel<<<MM + PP, THREADS>>>(embeds, cents, out, loss_elems);
    gemm_min_kernel<<<GRID, THREADS, SMEM_BYTES>>>();
    sqrt_kernel<<<(MM + 255) / 256, 256>>>(out, loss_elems);
}